// round 16
// baseline (speedup 1.0000x reference)
#include <cuda_runtime.h>
#include <cuda_bf16.h>
#include <cstdint>

// MvCnnDownLayer via mma.sync bf16 2-split (3 products, fp32 accum).
// 8-CTA clusters, 4-ROW TRAPEZOID: one barrier.cluster per 4 rows.
//   out[b,h] = relu(conv1dW(in[b,h] + out[b,h-1]) + bias)
// B=16,H=256,W=256,C=32,K=5. Grid 128 = 16 clusters x 8 CTAs, 384 thr.
// CTA owns 32 interior x but computes 48 positions lx in [-8,40)
// (3 m16-tiles); state validity shrinks 2/row from [-8,40) to [0,32) over a
// 4-row group (redundant halo compute, bitwise equal to neighbors').
// State ring: 8 buffers (row & 7) of 52 rows (ax = lx+10) x 80B, bf16 hi/lo.
// Group end: push 8 edge columns to each neighbor; local writes skip the
// push region (edge ranks keep masked zeros). In-group sync = __syncthreads.
// Warp (tile 0-2, ocq4 0-3): 10 k-tiles, 8 oc, 30 MMA, chain depth 10,
// W fragments hoisted. Depth-2 guarded input prefetch.

#define Bn 16
#define Hn 256
#define Wn 256
#define Cn 32
#define NT 384

#define ROWB 80u                     // bytes per A/W SMEM row (32 bf16 + pad)
#define ABUF (52u * ROWB)            // 4160: one state buffer (52 ax rows)
#define OFF_AH 0u                    // 8 bufs
#define OFF_AL (8u * ABUF)           // 33280, 8 bufs
#define OFF_WH (16u * ABUF)          // 66560, 160 rows x 80B
#define OFF_WL (OFF_WH + 12800u)     // 79360
#define SMEM_BYTES (OFF_WL + 12800u) // 92160

__device__ __forceinline__ void ldm4(uint32_t a, uint32_t r[4]) {
    asm volatile("ldmatrix.sync.aligned.m8n8.x4.shared.b16 {%0,%1,%2,%3}, [%4];"
                 : "=r"(r[0]), "=r"(r[1]), "=r"(r[2]), "=r"(r[3]) : "r"(a));
}
__device__ __forceinline__ void ldm2t(uint32_t a, uint32_t r[2]) {
    asm volatile("ldmatrix.sync.aligned.m8n8.x2.trans.shared.b16 {%0,%1}, [%2];"
                 : "=r"(r[0]), "=r"(r[1]) : "r"(a));
}
__device__ __forceinline__ void mma16816(float d[4], const uint32_t a[4],
                                         uint32_t b0, uint32_t b1) {
    asm volatile("mma.sync.aligned.m16n8k16.row.col.f32.bf16.bf16.f32 "
                 "{%0,%1,%2,%3}, {%4,%5,%6,%7}, {%8,%9}, {%0,%1,%2,%3};"
                 : "+f"(d[0]), "+f"(d[1]), "+f"(d[2]), "+f"(d[3])
                 : "r"(a[0]), "r"(a[1]), "r"(a[2]), "r"(a[3]), "r"(b0), "r"(b1));
}
__device__ __forceinline__ uint32_t pack2(float lo, float hi) {
    uint32_t r;
    asm("cvt.rn.satfinite.bf16x2.f32 %0, %1, %2;" : "=r"(r) : "f"(hi), "f"(lo));
    return r;
}
__device__ __forceinline__ float bf16rt(float x) {
    return __bfloat162float(__float2bfloat16(x));
}

__global__ void __cluster_dims__(8, 1, 1) __launch_bounds__(NT, 1)
mvcnn_mma9_kernel(const float* __restrict__ in, const float* __restrict__ wg,
                  const float* __restrict__ bias, float* __restrict__ out)
{
    extern __shared__ char smb[];
    const uint32_t smem = (uint32_t)__cvta_generic_to_shared(smb);

    const int tid  = threadIdx.x;
    const int lane = tid & 31;
    const int wid  = tid >> 5;          // 0..11
    const int tile = wid >> 2;          // 0..2
    const int ocq4 = wid & 3;           // oc quarter
    const int b    = blockIdx.x >> 3;
    const int rank = blockIdx.x & 7;
    const int seg  = rank * 32;

    const int q   = lane & 3;
    const int xr  = lane >> 2;
    const int ocq = ocq4 * 8 + q * 2;   // this thread's oc pair
    const int lx0 = tile * 16 - 8 + xr; // positions: lx0, lx0 + 8

    // --- stage weights: row = k*32+c, col = oc; bf16 hi/lo planes ---
    for (int idx = tid; idx < 5 * Cn * Cn; idx += NT) {
        int oc = idx & 31, ck = idx >> 5, k = ck % 5, c = ck / 5;
        float w  = wg[idx];
        float hf = bf16rt(w);
        uint32_t off = (uint32_t)(k * 32 + c) * ROWB + (uint32_t)oc * 2u;
        *(__nv_bfloat16*)(smb + OFF_WH + off) = __float2bfloat16(hf);
        *(__nv_bfloat16*)(smb + OFF_WL + off) = __float2bfloat16(w - hf);
    }

    // --- zero the permanent pad rows ax {0,1,50,51} of ALL 8 bufs, both planes ---
    for (int idx = tid; idx < 1280; idx += NT) {
        int word = idx % 20;
        int rsel = idx / 20;            // 0..63
        int rw   = rsel & 3;
        int buf  = (rsel >> 2) & 7;
        int pl   = rsel >> 5;
        uint32_t ax  = (rw < 2) ? (uint32_t)rw : (uint32_t)(48 + rw);
        uint32_t off = (pl ? OFF_AL : OFF_AH) + (uint32_t)buf * ABUF
                     + ax * ROWB + (uint32_t)word * 4u;
        *(uint32_t*)(smb + off) = 0u;
    }

    const size_t bHW = (size_t)b * Hn * Wn;

    // --- per-thread constants for the 2 owned positions ---
    int   gxs[2];
    bool  stg[2], ldok[2], wr3[2], pL[2], pR[2];
    float maskf[2];
    uint32_t soff[2], roffL[2], roffR[2];
#pragma unroll
    for (int s = 0; s < 2; ++s) {
        int lx = lx0 + 8 * s;
        int gx = seg + lx;
        gxs[s]   = gx;
        stg[s]   = (lx >= 0) && (lx < 32);
        ldok[s]  = (gx >= 0) && (gx < Wn);
        maskf[s] = ldok[s] ? 1.0f : 0.0f;
        // group-end local-write predicate: interior, or edge-of-image halo
        wr3[s]   = stg[s] || (lx < 0 && rank == 0) || (lx >= 32 && rank == 7);
        pL[s]    = (lx >= 0 && lx < 8)  && (rank > 0);  // -> left nbr ax lx+42
        pR[s]    = (lx >= 24 && lx < 32) && (rank < 7); // -> right nbr ax lx-22
        soff[s]  = (uint32_t)(lx + 10) * ROWB + (uint32_t)ocq * 2u;
        roffL[s] = (uint32_t)(lx + 42) * ROWB + (uint32_t)ocq * 2u;
        roffR[s] = (uint32_t)(lx - 22) * ROWB + (uint32_t)ocq * 2u;
    }

    // --- bias for this thread's 2 channels ---
    float2 bvt = *(const float2*)(bias + ocq);
    const float bv0 = bvt.x, bv1 = bvt.y;

    const uint32_t frag_base = (uint32_t)(lane & 15) * ROWB + (uint32_t)(lane >> 4) * 16u;

    // --- state_0 = in[0] into buf 0 (guarded + masked) ---
#pragma unroll
    for (int s = 0; s < 2; ++s) {
        float2 v = make_float2(0.f, 0.f);
        if (ldok[s]) v = *(const float2*)(in + (bHW + gxs[s]) * Cn + ocq);
        float h0 = bf16rt(v.x), h1 = bf16rt(v.y);
        *(uint32_t*)(smb + OFF_AH + soff[s]) = pack2(h0, h1);
        *(uint32_t*)(smb + OFF_AL + soff[s]) = pack2(v.x - h0, v.y - h1);
    }
    __syncthreads();
    asm volatile("barrier.cluster.arrive.aligned;\n\tbarrier.cluster.wait.aligned;" ::: "memory");

    // --- remote SMEM bases of neighbor CTAs ---
    uint32_t rbaseL = 0, rbaseR = 0;
    if (rank > 0)
        asm("mapa.shared::cluster.u32 %0, %1, %2;" : "=r"(rbaseL) : "r"(smem), "r"(rank - 1));
    if (rank < 7)
        asm("mapa.shared::cluster.u32 %0, %1, %2;" : "=r"(rbaseR) : "r"(smem), "r"(rank + 1));

    // --- hoist Wh + Wl fragments (row-invariant): 10 kt x 2 regs each ---
    const uint32_t wHb = smem + OFF_WH + frag_base + (uint32_t)ocq4 * 16u;
    const uint32_t wLb = smem + OFF_WL + frag_base + (uint32_t)ocq4 * 16u;
    uint32_t whf[10][2], wlf[10][2];
#pragma unroll
    for (int kt = 0; kt < 10; ++kt) {
        ldm2t(wHb + (uint32_t)kt * (16u * ROWB), whf[kt]);
        ldm2t(wLb + (uint32_t)kt * (16u * ROWB), wlf[kt]);
    }

    // --- depth-2 prefetch: cur = in[i+1] (guarded) ---
    float2 cur[2];
#pragma unroll
    for (int s = 0; s < 2; ++s) {
        cur[s] = make_float2(0.f, 0.f);
        if (ldok[s])
            cur[s] = *(const float2*)(in + (bHW + (size_t)1 * Wn + gxs[s]) * Cn + ocq);
    }

    for (int i = 0; i < Hn; ++i) {
        const int  r    = i & 3;
        const int  pbuf = i & 7;
        const int  wbuf = (i + 1) & 7;
        const bool more = (i + 1 < Hn);
        const bool last = (r == 3);

        // prefetch in[i+2] (guarded; consumed next row)
        float2 nxt[2];
        nxt[0] = make_float2(0.f, 0.f);
        nxt[1] = nxt[0];
        if (i + 2 < Hn) {
#pragma unroll
            for (int s = 0; s < 2; ++s)
                if (ldok[s])
                    nxt[s] = *(const float2*)(in + (bHW + (size_t)(i + 2) * Wn + gxs[s]) * Cn + ocq);
        }

        // --- conv: 10 k-tiles, 3 product-split accumulators ---
        float dHH[4], dHL[4], dLH[4];
#pragma unroll
        for (int e = 0; e < 4; ++e) { dHH[e] = 0.f; dHL[e] = 0.f; dLH[e] = 0.f; }

        const uint32_t aH = smem + OFF_AH + (uint32_t)pbuf * ABUF + frag_base;
        const uint32_t aL = smem + OFF_AL + (uint32_t)pbuf * ABUF + frag_base;

#pragma unroll
        for (int kt = 0; kt < 10; ++kt) {
            const int k = kt >> 1, ch = kt & 1;
            const uint32_t aoff = (uint32_t)(tile * 16 + k) * ROWB + (uint32_t)ch * 32u;
            uint32_t ah[4], al[4];
            ldm4(aH + aoff, ah);
            ldm4(aL + aoff, al);
            mma16816(dHH, ah, whf[kt][0], whf[kt][1]);
            mma16816(dHL, ah, wlf[kt][0], wlf[kt][1]);
            mma16816(dLH, al, whf[kt][0], whf[kt][1]);
        }

        // --- epilogue: state build (+ group-end halo push), STG, sync ---
        const uint32_t wAH = OFF_AH + (uint32_t)wbuf * ABUF;
        const uint32_t wAL = OFF_AL + (uint32_t)wbuf * ABUF;
        float v0s[2], v1s[2];
#pragma unroll
        for (int s = 0; s < 2; ++s) {
            float v0 = fmaxf(dHH[2 * s + 0] + dHL[2 * s + 0] + dLH[2 * s + 0] + bv0, 0.f);
            float v1 = fmaxf(dHH[2 * s + 1] + dHL[2 * s + 1] + dLH[2 * s + 1] + bv1, 0.f);
            v0s[s] = v0; v1s[s] = v1;
            if (more) {
                float xn0 = (v0 + cur[s].x) * maskf[s];
                float xn1 = (v1 + cur[s].y) * maskf[s];
                float h0 = bf16rt(xn0), h1 = bf16rt(xn1);
                uint32_t ph = pack2(h0, h1);
                uint32_t pl = pack2(xn0 - h0, xn1 - h1);
                // local write: always in-group; at group end skip the region a
                // neighbor will push into (edge ranks keep their masked zeros)
                if (!last || wr3[s]) {
                    *(uint32_t*)(smb + wAH + soff[s]) = ph;
                    *(uint32_t*)(smb + wAL + soff[s]) = pl;
                }
                if (last) {
                    if (pL[s]) {
                        asm volatile("st.shared::cluster.b32 [%0], %1;"
                                     :: "r"(rbaseL + wAH + roffL[s]), "r"(ph) : "memory");
                        asm volatile("st.shared::cluster.b32 [%0], %1;"
                                     :: "r"(rbaseL + wAL + roffL[s]), "r"(pl) : "memory");
                    }
                    if (pR[s]) {
                        asm volatile("st.shared::cluster.b32 [%0], %1;"
                                     :: "r"(rbaseR + wAH + roffR[s]), "r"(ph) : "memory");
                        asm volatile("st.shared::cluster.b32 [%0], %1;"
                                     :: "r"(rbaseR + wAL + roffR[s]), "r"(pl) : "memory");
                    }
                }
            }
        }

        // output store (interior positions only)
        float* op = out + (bHW + (size_t)i * Wn) * Cn;
#pragma unroll
        for (int s = 0; s < 2; ++s)
            if (stg[s])
                *(float2*)(op + (size_t)gxs[s] * Cn + ocq) = make_float2(v0s[s], v1s[s]);

        cur[0] = nxt[0]; cur[1] = nxt[1];

        // sync: cheap CTA barrier in-group; full cluster barrier at group end
        if (more) {
            if (last)
                asm volatile("barrier.cluster.arrive.aligned;\n\tbarrier.cluster.wait.aligned;"
                             ::: "memory");
            else
                __syncthreads();
        }
    }
}

extern "C" void kernel_launch(void* const* d_in, const int* in_sizes, int n_in,
                              void* d_out, int out_size)
{
    const float* in   = (const float*)d_in[0];
    const float* w    = (const float*)d_in[1];
    const float* bias = (const float*)d_in[2];
    float* out        = (float*)d_out;
    (void)in_sizes; (void)n_in; (void)out_size;

    cudaFuncSetAttribute(mvcnn_mma9_kernel,
                         cudaFuncAttributeMaxDynamicSharedMemorySize, SMEM_BYTES);
    mvcnn_mma9_kernel<<<dim3(Bn * 8), dim3(NT), SMEM_BYTES>>>(in, w, bias, out);
}

// round 17
// speedup vs baseline: 1.4060x; 1.4060x over previous
#include <cuda_runtime.h>
#include <cuda_bf16.h>
#include <cstdint>

// MvCnnDownLayer via mma.sync bf16 2-split (3 products, fp32 accum).
// 8-CTA clusters, oc-quarter warps, W fragments hoisted, depth-2 prefetch,
// 6 kt-parity-split accumulator chains (depth 5) + 2-stage A-fragment pipeline:
//   out[b,h] = relu(conv1dW(in[b,h] + out[b,h-1]) + bias)
// B=16,H=256,W=256,C=32,K=5. Grid 128 = 16 clusters x 8 CTAs, 256 thr.
// CTA owns 32 x (2 m16-tiles); A = X row bf16 hi/lo planes, 36 rows
// (2 halo each side), 80B stride. Warp (tile 0-1, ocq 0-3): 10 k-tiles, 8 oc.
// One barrier.cluster per row is the only sync (structure identical to R14).

#define Bn 16
#define Hn 256
#define Wn 256
#define Cn 32
#define NT 256

#define ROWB 80u                    // bytes per A/W SMEM row (32 bf16 + pad)
#define APAR (36u * ROWB)           // 2880 per parity per plane
#define OFF_AH 0u
#define OFF_AL 5760u
#define OFF_WH 11520u               // 160 rows x 80B
#define OFF_WL 24320u
#define SMEM_BYTES 37120u

__device__ __forceinline__ void ldm4(uint32_t a, uint32_t r[4]) {
    asm volatile("ldmatrix.sync.aligned.m8n8.x4.shared.b16 {%0,%1,%2,%3}, [%4];"
                 : "=r"(r[0]), "=r"(r[1]), "=r"(r[2]), "=r"(r[3]) : "r"(a));
}
__device__ __forceinline__ void ldm2t(uint32_t a, uint32_t r[2]) {
    asm volatile("ldmatrix.sync.aligned.m8n8.x2.trans.shared.b16 {%0,%1}, [%2];"
                 : "=r"(r[0]), "=r"(r[1]) : "r"(a));
}
__device__ __forceinline__ void mma16816(float d[4], const uint32_t a[4],
                                         uint32_t b0, uint32_t b1) {
    asm volatile("mma.sync.aligned.m16n8k16.row.col.f32.bf16.bf16.f32 "
                 "{%0,%1,%2,%3}, {%4,%5,%6,%7}, {%8,%9}, {%0,%1,%2,%3};"
                 : "+f"(d[0]), "+f"(d[1]), "+f"(d[2]), "+f"(d[3])
                 : "r"(a[0]), "r"(a[1]), "r"(a[2]), "r"(a[3]), "r"(b0), "r"(b1));
}
__device__ __forceinline__ uint32_t pack2(float lo, float hi) {
    uint32_t r;
    asm("cvt.rn.satfinite.bf16x2.f32 %0, %1, %2;" : "=r"(r) : "f"(hi), "f"(lo));
    return r;
}
__device__ __forceinline__ float bf16rt(float x) {
    return __bfloat162float(__float2bfloat16(x));
}

__global__ void __cluster_dims__(8, 1, 1) __launch_bounds__(NT, 1)
mvcnn_mma10_kernel(const float* __restrict__ in, const float* __restrict__ wg,
                   const float* __restrict__ bias, float* __restrict__ out)
{
    extern __shared__ char smb[];
    const uint32_t smem = (uint32_t)__cvta_generic_to_shared(smb);

    const int tid  = threadIdx.x;
    const int lane = tid & 31;
    const int wid  = tid >> 5;          // 0..7
    const int tile = wid & 1;           // m16-tile within 32-x segment
    const int ocq4 = wid >> 1;          // oc quarter 0..3
    const int b    = blockIdx.x >> 3;
    const int rank = blockIdx.x & 7;
    const int seg  = rank * 32;

    const int q   = lane & 3;
    const int xr  = lane >> 2;
    const int ocq = ocq4 * 8 + q * 2;   // this thread's oc pair
    const int xl0 = tile * 16 + xr;     // local x; this thread: xl0, xl0+8

    // --- stage weights: row = k*32+c, col = oc; bf16 hi/lo planes ---
    for (int idx = tid; idx < 5 * Cn * Cn; idx += NT) {
        int oc = idx & 31, ck = idx >> 5, k = ck % 5, c = ck / 5;
        float w  = wg[idx];
        float hf = bf16rt(w);
        uint32_t off = (uint32_t)(k * 32 + c) * ROWB + (uint32_t)oc * 2u;
        *(__nv_bfloat16*)(smb + OFF_WH + off) = __float2bfloat16(hf);
        *(__nv_bfloat16*)(smb + OFF_WL + off) = __float2bfloat16(w - hf);
    }

    const size_t bHW = (size_t)b * Hn * Wn;

    // --- halo rows ax in {0,1,34,35}: interior -> load row 0 (parity 0);
    //     edge-of-image -> zero BOTH parities (never rewritten) ---
    if (tid < 128) {
        int par  = tid >> 6;            // 0,1
        int side = (tid >> 5) & 1;      // 0=left, 1=right
        int rr   = (tid >> 4) & 1;      // row within side
        int cp   = tid & 15;            // channel pair
        uint32_t ax = side ? (uint32_t)(34 + rr) : (uint32_t)rr;
        int gx = seg + (side ? 32 + rr : rr - 2);
        bool valid = (gx >= 0) && (gx < Wn);
        uint32_t off = (uint32_t)par * APAR + ax * ROWB + (uint32_t)cp * 4u;
        if (!valid) {
            *(uint32_t*)(smb + OFF_AH + off) = 0u;
            *(uint32_t*)(smb + OFF_AL + off) = 0u;
        } else if (par == 0) {
            float2 v = *(const float2*)(in + (bHW + gx) * Cn + cp * 2);
            float h0 = bf16rt(v.x), h1 = bf16rt(v.y);
            *(uint32_t*)(smb + OFF_AH + off) = pack2(h0, h1);
            *(uint32_t*)(smb + OFF_AL + off) = pack2(v.x - h0, v.y - h1);
        }
    }

    // --- bias for this thread's 2 channels ---
    float2 bvt = *(const float2*)(bias + ocq);
    const float bv0 = bvt.x, bv1 = bvt.y;

    const uint32_t frag_base = (uint32_t)(lane & 15) * ROWB + (uint32_t)(lane >> 4) * 16u;

    // --- row-0 interior state = in[0] ---
#pragma unroll
    for (int s = 0; s < 2; ++s) {
        int lx = xl0 + s * 8;
        const float* ip = in + (bHW + (seg + lx)) * Cn + ocq;
        float2 v = *(const float2*)ip;
        float h0 = bf16rt(v.x), h1 = bf16rt(v.y);
        uint32_t off = (uint32_t)(lx + 2) * ROWB + (uint32_t)ocq * 2u;
        *(uint32_t*)(smb + OFF_AH + off) = pack2(h0, h1);
        *(uint32_t*)(smb + OFF_AL + off) = pack2(v.x - h0, v.y - h1);
    }
    __syncthreads();

    // --- remote SMEM bases of neighbor CTAs ---
    uint32_t rbaseL = 0, rbaseR = 0;
    if (rank > 0)
        asm("mapa.shared::cluster.u32 %0, %1, %2;" : "=r"(rbaseL) : "r"(smem), "r"(rank - 1));
    if (rank < 7)
        asm("mapa.shared::cluster.u32 %0, %1, %2;" : "=r"(rbaseR) : "r"(smem), "r"(rank + 1));

    // --- hoist Wh + Wl fragments (row-invariant): 10 kt x 2 regs each ---
    const uint32_t wHb = smem + OFF_WH + frag_base + (uint32_t)ocq4 * 16u;
    const uint32_t wLb = smem + OFF_WL + frag_base + (uint32_t)ocq4 * 16u;
    uint32_t whf[10][2], wlf[10][2];
#pragma unroll
    for (int kt = 0; kt < 10; ++kt) {
        ldm2t(wHb + (uint32_t)kt * (16u * ROWB), whf[kt]);
        ldm2t(wLb + (uint32_t)kt * (16u * ROWB), wlf[kt]);
    }

    // --- depth-2 prefetch pipeline: cur = in[i+1] (in regs) ---
    float2 cur[2];
#pragma unroll
    for (int s = 0; s < 2; ++s)
        cur[s] = *(const float2*)(in + (bHW + (size_t)1 * Wn + (seg + xl0 + s * 8)) * Cn + ocq);

    // per-kt A offsets (compile-time pattern)
    const uint32_t aRowBase = (uint32_t)(tile * 16) * ROWB;

    for (int i = 0; i < Hn; ++i) {
        const int  p    = i & 1;
        const bool more = (i + 1 < Hn);

        // issue prefetch for in[i+2] (consumed next row)
        float2 nxt[2];
        if (i + 2 < Hn) {
#pragma unroll
            for (int s = 0; s < 2; ++s)
                nxt[s] = *(const float2*)(in + (bHW + (size_t)(i + 2) * Wn
                                                + (seg + xl0 + s * 8)) * Cn + ocq);
        }

        // 6 kt-parity-split accumulator chains (depth 5 each)
        float dHH[2][4], dHL[2][4], dLH[2][4];
#pragma unroll
        for (int e = 0; e < 4; ++e) {
            dHH[0][e] = 0.f; dHH[1][e] = 0.f;
            dHL[0][e] = 0.f; dHL[1][e] = 0.f;
            dLH[0][e] = 0.f; dLH[1][e] = 0.f;
        }

        const uint32_t aH = smem + OFF_AH + (uint32_t)p * APAR + frag_base + aRowBase;
        const uint32_t aL = smem + OFF_AL + (uint32_t)p * APAR + frag_base + aRowBase;

        // --- 2-stage software pipeline over 10 k-tiles ---
        uint32_t ahb[2][4], alb[2][4];
        // kt=0: aoff = 0*ROWB + 0
        ldm4(aH, ahb[0]);
        ldm4(aL, alb[0]);
#pragma unroll
        for (int kt = 0; kt < 10; ++kt) {
            const int cb = kt & 1;
            if (kt < 9) {
                const int kn = kt + 1;
                const uint32_t aoff = (uint32_t)(kn >> 1) * ROWB + (uint32_t)(kn & 1) * 32u;
                ldm4(aH + aoff, ahb[cb ^ 1]);
                ldm4(aL + aoff, alb[cb ^ 1]);
            }
            mma16816(dHH[cb], ahb[cb], whf[kt][0], whf[kt][1]);
            mma16816(dHL[cb], ahb[cb], wlf[kt][0], wlf[kt][1]);
            mma16816(dLH[cb], alb[cb], whf[kt][0], whf[kt][1]);
        }

        // --- epilogue: state build + halo push FIRST (early arrive), STG after ---
        float v0s[2], v1s[2];
        const uint32_t wAH = OFF_AH + (uint32_t)(p ^ 1) * APAR;
        const uint32_t wAL = OFF_AL + (uint32_t)(p ^ 1) * APAR;
#pragma unroll
        for (int s = 0; s < 2; ++s) {
            const int lx = xl0 + s * 8;
            float a0 = (dHH[0][2 * s + 0] + dHH[1][2 * s + 0])
                     + (dHL[0][2 * s + 0] + dHL[1][2 * s + 0])
                     + (dLH[0][2 * s + 0] + dLH[1][2 * s + 0]);
            float a1 = (dHH[0][2 * s + 1] + dHH[1][2 * s + 1])
                     + (dHL[0][2 * s + 1] + dHL[1][2 * s + 1])
                     + (dLH[0][2 * s + 1] + dLH[1][2 * s + 1]);
            float v0 = fmaxf(a0 + bv0, 0.f);
            float v1 = fmaxf(a1 + bv1, 0.f);
            v0s[s] = v0; v1s[s] = v1;
            if (more) {
                float xn0 = v0 + cur[s].x;
                float xn1 = v1 + cur[s].y;
                float h0 = bf16rt(xn0), h1 = bf16rt(xn1);
                uint32_t ph = pack2(h0, h1);
                uint32_t pl = pack2(xn0 - h0, xn1 - h1);
                uint32_t off = (uint32_t)(lx + 2) * ROWB + (uint32_t)ocq * 2u;
                *(uint32_t*)(smb + wAH + off) = ph;
                *(uint32_t*)(smb + wAL + off) = pl;
                if (lx < 2 && rank > 0) {       // -> left neighbor ax 34,35
                    uint32_t roff = (uint32_t)(34 + lx) * ROWB + (uint32_t)ocq * 2u;
                    asm volatile("st.shared::cluster.b32 [%0], %1;"
                                 :: "r"(rbaseL + wAH + roff), "r"(ph) : "memory");
                    asm volatile("st.shared::cluster.b32 [%0], %1;"
                                 :: "r"(rbaseL + wAL + roff), "r"(pl) : "memory");
                }
                if (lx >= 30 && rank < 7) {     // -> right neighbor ax 0,1
                    uint32_t roff = (uint32_t)(lx - 30) * ROWB + (uint32_t)ocq * 2u;
                    asm volatile("st.shared::cluster.b32 [%0], %1;"
                                 :: "r"(rbaseR + wAH + roff), "r"(ph) : "memory");
                    asm volatile("st.shared::cluster.b32 [%0], %1;"
                                 :: "r"(rbaseR + wAL + roff), "r"(pl) : "memory");
                }
            }
        }

        // output store + prefetch rotate (off the inter-CTA critical path)
        float* op = out + (bHW + (size_t)i * Wn) * Cn;
#pragma unroll
        for (int s = 0; s < 2; ++s)
            *(float2*)(op + (size_t)(seg + xl0 + s * 8) * Cn + ocq)
                = make_float2(v0s[s], v1s[s]);
        cur[0] = nxt[0]; cur[1] = nxt[1];

        // single per-row sync: cluster-wide barrier
        if (more)
            asm volatile("barrier.cluster.arrive.aligned;\n\tbarrier.cluster.wait.aligned;"
                         ::: "memory");
    }
}

extern "C" void kernel_launch(void* const* d_in, const int* in_sizes, int n_in,
                              void* d_out, int out_size)
{
    const float* in   = (const float*)d_in[0];
    const float* w    = (const float*)d_in[1];
    const float* bias = (const float*)d_in[2];
    float* out        = (float*)d_out;
    (void)in_sizes; (void)n_in; (void)out_size;

    cudaFuncSetAttribute(mvcnn_mma10_kernel,
                         cudaFuncAttributeMaxDynamicSharedMemorySize, SMEM_BYTES);
    mvcnn_mma10_kernel<<<dim3(Bn * 8), dim3(NT), SMEM_BYTES>>>(in, w, bias, out);
}